// round 16
// baseline (speedup 1.0000x reference)
#include <cuda_runtime.h>

// Problem constants (fixed by setup_inputs): B=1, N=768, C_IN=C_OUT=16, R=8
#define N_PTS 768
#define CIN   16
#define COUT  16
#define RB    8

#define TA      8            // a-rows per CTA
#define BBC     16           // b per chunk
#define NBSPLIT 3            // b-range splits (grid.y)
#define BPC     (N_PTS / NBSPLIT)   // 256 b per CTA
#define NCHUNK  (BPC / BBC)         // 16 chunks

// scratch: h[b][r][i] (pre-scaled by 1/sqrt(n_norm))
__device__ float g_h[N_PTS * RB * COUT];

// ---------------------------------------------------------------------------
// Kernel A: h[b,r,i] = (1/sqrt(n_norm)) * sum_j W[r,i,j] * f[b,j]
// grid = 768 blocks, 128 threads; thread t = r*16 + i
// ---------------------------------------------------------------------------
__global__ void precompute_h_kernel(const float* __restrict__ f,
                                    const float* __restrict__ W,
                                    const int*   __restrict__ n_norm_ptr) {
    __shared__ float fb[CIN];
    const int b = blockIdx.x;
    const int t = threadIdx.x;          // 0..127  (= r*16 + i)
    if (t < CIN) fb[t] = f[b * CIN + t];
    __syncthreads();

    // n_norm may arrive as int32 (expected) or float32 bits; detect robustly.
    int   iv = n_norm_ptr[0];
    float nn = (iv > 0 && iv < 100000000) ? (float)iv : __int_as_float(iv);
    float scale = rsqrtf(nn);

    const float4* w4 = (const float4*)(W + t * CIN);   // W[r][i][0..15]
    float acc = 0.0f;
#pragma unroll
    for (int q = 0; q < 4; q++) {
        float4 w = w4[q];
        acc = fmaf(w.x, fb[q * 4 + 0], acc);
        acc = fmaf(w.y, fb[q * 4 + 1], acc);
        acc = fmaf(w.z, fb[q * 4 + 2], acc);
        acc = fmaf(w.w, fb[q * 4 + 3], acc);
    }
    g_h[b * (RB * COUT) + t] = acc * scale;
}

// ---------------------------------------------------------------------------
// Kernel B: out[a,i] += sum_{b in split} sum_r rbf(a,b,r) * h[b,r,i]
// block = 128 threads: tid = bg*32 + a_local*4 + iq
//   bg      (warp id, 0..3): quarter of the 16-b chunk in the contraction
//   a_local (0..7)          : which of the CTA's 8 a-rows
//   iq      (0..3)          : float4 group of output channels (i = iq*4+k)
// grid = (768/TA, NBSPLIT) = (96, 3)
// ---------------------------------------------------------------------------
__global__ void __launch_bounds__(128, 2)
conv_main_kernel(const float* __restrict__ geom,
                 const float* __restrict__ mu,
                 const float* __restrict__ gamma,
                 float* __restrict__ out) {
    // smem: geometry 9216 + h 8192 + rbf 4224 + mu/ga 64 + red 2048 ~= 23.7 KB
    __shared__ float  sh_g[N_PTS * 3];
    __shared__ float  sh_h[BBC * RB * COUT];          // [bb][r][i] linear
    __shared__ float  sh_rbf[TA][BBC * RB + 4];       // pitch 132 words (anti-conflict pad)
    __shared__ float  sh_mu[RB], sh_ga[RB];
    __shared__ float4 sh_red[128];

    const int tid     = threadIdx.x;
    const int iq      = tid & 3;
    const int a_local = (tid >> 2) & 7;
    const int bg      = tid >> 5;

    const int a0      = blockIdx.x * TA;
    const int b_start = blockIdx.y * BPC;

    // stage all geometry + RBF params once
    for (int k = tid; k < N_PTS * 3; k += 128) sh_g[k] = geom[k];
    if (tid < RB) { sh_mu[tid] = mu[tid]; sh_ga[tid] = gamma[tid]; }
    __syncthreads();

    // rbf-phase role: thread = (a2, b2) pair within the 8x16 chunk
    const int a2 = tid >> 4;     // 0..7
    const int b2 = tid & 15;     // 0..15
    const float gax = sh_g[(a0 + a2) * 3 + 0];
    const float gay = sh_g[(a0 + a2) * 3 + 1];
    const float gaz = sh_g[(a0 + a2) * 3 + 2];

    float4 acc = make_float4(0.f, 0.f, 0.f, 0.f);

    for (int c = 0; c < NCHUNK; c++) {
        const int b0 = b_start + c * BBC;

        // 1) stage h chunk: 2048 floats = 512 float4, 4 per thread (coalesced)
        {
            const float4* hg4 = (const float4*)(g_h + b0 * (RB * COUT));
            float4*       hs4 = (float4*)sh_h;
#pragma unroll
            for (int q = 0; q < 4; q++)
                hs4[tid + q * 128] = hg4[tid + q * 128];
        }

        // 2) rbf for all 8x16 pairs: exactly one exp per (a,b,r), no redundancy
        {
            const int b = b0 + b2;
            const float dx = sh_g[b * 3 + 0] - gax;
            const float dy = sh_g[b * 3 + 1] - gay;
            const float dz = sh_g[b * 3 + 2] - gaz;
            const float d  = sqrtf(fmaf(dx, dx, fmaf(dy, dy, fmaf(dz, dz, 1e-9f))));
            float* rp = &sh_rbf[a2][b2 * RB];
            float rv[RB];
#pragma unroll
            for (int r = 0; r < RB; r++) {
                const float dd = d - sh_mu[r];
                rv[r] = __expf(-sh_ga[r] * dd * dd);
            }
            ((float4*)rp)[0] = make_float4(rv[0], rv[1], rv[2], rv[3]);
            ((float4*)rp)[1] = make_float4(rv[4], rv[5], rv[6], rv[7]);
        }
        __syncthreads();

        // 3) contraction: warp bg owns 4 of the 16 b's
#pragma unroll
        for (int u = 0; u < 4; u++) {
            const int bb = bg * 4 + u;
            const float4* rv4 = (const float4*)&sh_rbf[a_local][bb * RB];
            const float4 r0 = rv4[0];
            const float4 r1 = rv4[1];
            const float4* hv4 = (const float4*)sh_h + bb * 32 + iq;  // [bb][r][iq*4..]
            float rr;
#pragma unroll
            for (int r = 0; r < RB; r++) {
                const float4 h = hv4[r * 4];
                switch (r) {
                    case 0: rr = r0.x; break; case 1: rr = r0.y; break;
                    case 2: rr = r0.z; break; case 3: rr = r0.w; break;
                    case 4: rr = r1.x; break; case 5: rr = r1.y; break;
                    case 6: rr = r1.z; break; default: rr = r1.w; break;
                }
                acc.x = fmaf(rr, h.x, acc.x);
                acc.y = fmaf(rr, h.y, acc.y);
                acc.z = fmaf(rr, h.z, acc.z);
                acc.w = fmaf(rr, h.w, acc.w);
            }
        }
        __syncthreads();   // protect sh_h / sh_rbf before next chunk overwrites
    }

    // 4) reduce the 4 bg-partials, then one atomicAdd per output float
    sh_red[tid] = acc;
    __syncthreads();
    if (bg == 0) {
        float4 s  = sh_red[tid];
        float4 s1 = sh_red[tid + 32];
        float4 s2 = sh_red[tid + 64];
        float4 s3 = sh_red[tid + 96];
        s.x += s1.x + s2.x + s3.x;
        s.y += s1.y + s2.y + s3.y;
        s.z += s1.z + s2.z + s3.z;
        s.w += s1.w + s2.w + s3.w;
        const int a  = a0 + a_local;
        float* op = &out[a * COUT + iq * 4];
        atomicAdd(op + 0, s.x);
        atomicAdd(op + 1, s.y);
        atomicAdd(op + 2, s.z);
        atomicAdd(op + 3, s.w);
    }
}

// ---------------------------------------------------------------------------
// Launch: inputs in metadata order:
//   0 features [1,768,16] f32 | 1 geometry [1,768,3] f32 | 2 W [8,16,16] f32
//   3 mu [8] f32 | 4 gamma [8] f32 | 5 n_norm scalar
// output: [1,768,16] f32
// ---------------------------------------------------------------------------
extern "C" void kernel_launch(void* const* d_in, const int* in_sizes, int n_in,
                              void* d_out, int out_size) {
    const float* features = (const float*)d_in[0];
    const float* geometry = (const float*)d_in[1];
    const float* W        = (const float*)d_in[2];
    const float* mu       = (const float*)d_in[3];
    const float* gamma    = (const float*)d_in[4];
    const int*   n_norm   = (const int*)d_in[5];
    float*       out      = (float*)d_out;

    // output is accumulated via atomicAdd across b-splits -> must start at 0
    cudaMemsetAsync(out, 0, (size_t)N_PTS * COUT * sizeof(float), 0);

    precompute_h_kernel<<<N_PTS, 128>>>(features, W, n_norm);

    dim3 grid(N_PTS / TA, NBSPLIT);   // (96, 3) = 288 CTAs
    conv_main_kernel<<<grid, 128>>>(geometry, mu, gamma, out);
}

// round 17
// speedup vs baseline: 1.1651x; 1.1651x over previous
#include <cuda_runtime.h>

// Problem constants (fixed by setup_inputs): B=1, N=768, C_IN=C_OUT=16, R=8
#define N_PTS 768
#define CIN   16
#define COUT  16
#define RB    8

#define TA      8                   // a-rows per CTA
#define BBC     16                  // b per chunk
#define NBSPLIT 6                   // b-range splits (grid.y)
#define BPC     (N_PTS / NBSPLIT)   // 128 b per CTA
#define NCHUNK  (BPC / BBC)         // 8 chunks
#define HCHUNK  (BBC * RB * COUT)   // 2048 floats per h chunk

// scratch: h[b][r][i] (pre-scaled by 1/sqrt(n_norm))
__device__ float g_h[N_PTS * RB * COUT];

__device__ __forceinline__ void cp_async16(void* smem_dst, const void* gmem_src) {
    unsigned s = (unsigned)__cvta_generic_to_shared(smem_dst);
    asm volatile("cp.async.cg.shared.global [%0], [%1], 16;\n" :: "r"(s), "l"(gmem_src));
}
__device__ __forceinline__ void cp_async_commit() {
    asm volatile("cp.async.commit_group;\n" ::: "memory");
}
__device__ __forceinline__ void cp_async_wait_all() {
    asm volatile("cp.async.wait_group 0;\n" ::: "memory");
}

// ---------------------------------------------------------------------------
// Kernel A: h[b,r,i] = (1/sqrt(n_norm)) * sum_j W[r,i,j] * f[b,j]
// grid = 768 blocks, 128 threads; thread t = r*16 + i
// ---------------------------------------------------------------------------
__global__ void precompute_h_kernel(const float* __restrict__ f,
                                    const float* __restrict__ W,
                                    const int*   __restrict__ n_norm_ptr) {
    __shared__ float fb[CIN];
    const int b = blockIdx.x;
    const int t = threadIdx.x;          // 0..127  (= r*16 + i)
    if (t < CIN) fb[t] = f[b * CIN + t];
    __syncthreads();

    // n_norm may arrive as int32 (expected) or float32 bits; detect robustly.
    int   iv = n_norm_ptr[0];
    float nn = (iv > 0 && iv < 100000000) ? (float)iv : __int_as_float(iv);
    float scale = rsqrtf(nn);

    const float4* w4 = (const float4*)(W + t * CIN);   // W[r][i][0..15]
    float acc = 0.0f;
#pragma unroll
    for (int q = 0; q < 4; q++) {
        float4 w = w4[q];
        acc = fmaf(w.x, fb[q * 4 + 0], acc);
        acc = fmaf(w.y, fb[q * 4 + 1], acc);
        acc = fmaf(w.z, fb[q * 4 + 2], acc);
        acc = fmaf(w.w, fb[q * 4 + 3], acc);
    }
    g_h[b * (RB * COUT) + t] = acc * scale;
}

// ---------------------------------------------------------------------------
// Kernel B: out[a,i] += sum_{b in split} sum_r rbf(a,b,r) * h[b,r,i]
// block = 128 threads:
//   contraction role: tid = bg*32 + a_local*4 + iq
//   rbf role:         tid = a2*16 + b2
// grid = (768/TA, NBSPLIT) = (96, 6). Double-buffered, 1 barrier per chunk.
// ---------------------------------------------------------------------------
__global__ void __launch_bounds__(128, 4)
conv_main_kernel(const float* __restrict__ geom,
                 const float* __restrict__ mu,
                 const float* __restrict__ gamma,
                 float* __restrict__ out) {
    __shared__ float  sh_gb[BPC * 3];                 // b-range geometry (1.5 KB)
    __shared__ float  sh_h[2][HCHUNK];                // ping-pong h chunks (16 KB)
    __shared__ float  sh_rbf[2][TA][BBC * RB + 4];    // ping-pong rbf (8.25 KB), pad=4
    __shared__ float  sh_mu[RB], sh_ga[RB];
    __shared__ float4 sh_red[128];

    const int tid     = threadIdx.x;
    const int iq      = tid & 3;
    const int a_local = (tid >> 2) & 7;
    const int bg      = tid >> 5;

    const int a0      = blockIdx.x * TA;
    const int b_start = blockIdx.y * BPC;

    // stage b-range geometry + RBF params
    for (int k = tid; k < BPC * 3; k += 128) sh_gb[k] = geom[b_start * 3 + k];
    if (tid < RB) { sh_mu[tid] = mu[tid]; sh_ga[tid] = gamma[tid]; }

    // rbf-phase role: thread = (a2, b2) within the 8x16 chunk; a-geometry from global
    const int a2 = tid >> 4;     // 0..7
    const int b2 = tid & 15;     // 0..15
    const float gax = __ldg(&geom[(a0 + a2) * 3 + 0]);
    const float gay = __ldg(&geom[(a0 + a2) * 3 + 1]);
    const float gaz = __ldg(&geom[(a0 + a2) * 3 + 2]);

    const float4* hg4_base = (const float4*)(g_h + b_start * (RB * COUT));

    // --- rbf computation for chunk c into buffer `buf` (one exp per a,b,r) ---
    auto compute_rbf = [&](int c, int buf) {
        const int bl = c * BBC + b2;                  // local b index
        const float dx = sh_gb[bl * 3 + 0] - gax;
        const float dy = sh_gb[bl * 3 + 1] - gay;
        const float dz = sh_gb[bl * 3 + 2] - gaz;
        const float d  = sqrtf(fmaf(dx, dx, fmaf(dy, dy, fmaf(dz, dz, 1e-9f))));
        float rv[RB];
#pragma unroll
        for (int r = 0; r < RB; r++) {
            const float dd = d - sh_mu[r];
            rv[r] = __expf(-sh_ga[r] * dd * dd);
        }
        float* rp = &sh_rbf[buf][a2][b2 * RB];
        ((float4*)rp)[0] = make_float4(rv[0], rv[1], rv[2], rv[3]);
        ((float4*)rp)[1] = make_float4(rv[4], rv[5], rv[6], rv[7]);
    };

    // --- async stage of h chunk c into sh_h[buf] (4 x 16B per thread) ---
    auto stage_h = [&](int c, int buf) {
        const float4* src = hg4_base + c * (HCHUNK / 4);
        float4*       dst = (float4*)sh_h[buf];
#pragma unroll
        for (int q = 0; q < 4; q++)
            cp_async16(&dst[tid + q * 128], &src[tid + q * 128]);
        cp_async_commit();
    };

    // prologue: chunk 0 (geometry staging is visible after the sync below)
    __syncthreads();                 // sh_gb / sh_mu ready for compute_rbf
    stage_h(0, 0);
    compute_rbf(0, 0);
    cp_async_wait_all();
    __syncthreads();

    float4 acc = make_float4(0.f, 0.f, 0.f, 0.f);

    for (int c = 0; c < NCHUNK; c++) {
        const int cur = c & 1, nxt = cur ^ 1;

        // kick off next chunk's h load first (overlaps with contraction)
        if (c + 1 < NCHUNK) stage_h(c + 1, nxt);

        // contraction on current buffers: warp bg owns 4 of the 16 b's
#pragma unroll
        for (int u = 0; u < 4; u++) {
            const int bb = bg * 4 + u;
            const float4* rv4 = (const float4*)&sh_rbf[cur][a_local][bb * RB];
            const float4 r0 = rv4[0];
            const float4 r1 = rv4[1];
            const float4* hv4 = (const float4*)sh_h[cur] + bb * 32 + iq;
            float rr;
#pragma unroll
            for (int r = 0; r < RB; r++) {
                const float4 h = hv4[r * 4];
                switch (r) {
                    case 0: rr = r0.x; break; case 1: rr = r0.y; break;
                    case 2: rr = r0.z; break; case 3: rr = r0.w; break;
                    case 4: rr = r1.x; break; case 5: rr = r1.y; break;
                    case 6: rr = r1.z; break; default: rr = r1.w; break;
                }
                acc.x = fmaf(rr, h.x, acc.x);
                acc.y = fmaf(rr, h.y, acc.y);
                acc.z = fmaf(rr, h.z, acc.z);
                acc.w = fmaf(rr, h.w, acc.w);
            }
        }

        // produce next chunk's rbf into the spare buffer (free since last sync)
        if (c + 1 < NCHUNK) compute_rbf(c + 1, nxt);

        cp_async_wait_all();
        __syncthreads();             // single barrier per chunk
    }

    // reduce the 4 bg-partials, then one atomicAdd per output float
    sh_red[tid] = acc;
    __syncthreads();
    if (bg == 0) {
        float4 s  = sh_red[tid];
        float4 s1 = sh_red[tid + 32];
        float4 s2 = sh_red[tid + 64];
        float4 s3 = sh_red[tid + 96];
        s.x += s1.x + s2.x + s3.x;
        s.y += s1.y + s2.y + s3.y;
        s.z += s1.z + s2.z + s3.z;
        s.w += s1.w + s2.w + s3.w;
        float* op = &out[(a0 + a_local) * COUT + iq * 4];
        atomicAdd(op + 0, s.x);
        atomicAdd(op + 1, s.y);
        atomicAdd(op + 2, s.z);
        atomicAdd(op + 3, s.w);
    }
}

// ---------------------------------------------------------------------------
// Launch: inputs in metadata order:
//   0 features [1,768,16] f32 | 1 geometry [1,768,3] f32 | 2 W [8,16,16] f32
//   3 mu [8] f32 | 4 gamma [8] f32 | 5 n_norm scalar
// output: [1,768,16] f32
// ---------------------------------------------------------------------------
extern "C" void kernel_launch(void* const* d_in, const int* in_sizes, int n_in,
                              void* d_out, int out_size) {
    const float* features = (const float*)d_in[0];
    const float* geometry = (const float*)d_in[1];
    const float* W        = (const float*)d_in[2];
    const float* mu       = (const float*)d_in[3];
    const float* gamma    = (const float*)d_in[4];
    const int*   n_norm   = (const int*)d_in[5];
    float*       out      = (float*)d_out;

    // output is accumulated via atomicAdd across b-splits -> must start at 0
    cudaMemsetAsync(out, 0, (size_t)N_PTS * COUT * sizeof(float), 0);

    precompute_h_kernel<<<N_PTS, 128>>>(features, W, n_norm);

    dim3 grid(N_PTS / TA, NBSPLIT);   // (96, 6) = 576 CTAs, ~4/SM in one wave
    conv_main_kernel<<<grid, 128>>>(geometry, mu, gamma, out);
}